// round 5
// baseline (speedup 1.0000x reference)
#include <cuda_runtime.h>

// ---------------------------------------------------------------------------
// CircularRelativePositionAttention  (B=8, S=1024, D=1024, H=16, HD=64)
//
// Decomposition (per (b,h) pair):
//   1) P[q,j]   = q_row . rel_pos_k[j]              (j = 0..512)   [k_relk]
//   2) scores   = scale * Q K^T + P[q, idx(q,k)], softmax -> attn  [k_scores]
//   3) out      = attn @ V                                         [k_av]
//   4) out     += Wfold @ rel_pos_v, where
//      Wfold[q,j] = attn[q,(q-j)%S] + (0<j<512 ? attn[q,(q+j)%S] : 0)
//                                                                  [k_wrelv]
// All fp32 on CUDA cores this round; scratch in __device__ globals.
// ---------------------------------------------------------------------------

#define Bn    8
#define Hn    16
#define BHn   128
#define Sn    1024
#define Dn    1024
#define HDn   64
#define Jn    513          // used rel indices 0..512
#define JPn   520          // padded row stride for P
#define SMASK 1023
#define SCALE 0.125f       // 1/sqrt(64)

// scratch: P bias table (~272 MB) and attention probabilities (512 MB)
__device__ float g_P[(size_t)BHn * Sn * JPn];
__device__ float g_attn[(size_t)BHn * Sn * Sn];

// ---------------------------------------------------------------------------
// Kernel 1: P[bh,q,j] = q_row . rel_pos_k[j]   (A,B both K-major, K=64)
// block tile: 32 rows x 128 cols; 256 threads; warp -> 4 rows, lane -> 4 cols
// ---------------------------------------------------------------------------
__global__ void __launch_bounds__(256) k_relk(const float* __restrict__ query,
                                              const float* __restrict__ relk) {
    __shared__ float sQ[32][68];
    __shared__ float sB[128][68];
    const int jt  = blockIdx.x;        // 0..4  (128 cols each, covers 640 >= 513)
    const int mt  = blockIdx.y;        // 0..4095 (32 rows each, M = 131072)
    const int tid = threadIdx.x;
    const int w   = tid >> 5, lx = tid & 31;

    for (int i = tid; i < 32 * 16; i += 256) {
        int r = i >> 4, v = i & 15;
        int gm = mt * 32 + r;
        int bh = gm >> 10, q = gm & SMASK;
        int b = bh >> 4, h = bh & 15;
        *(float4*)&sQ[r][4 * v] =
            *(const float4*)&query[((size_t)b * Sn + q) * Dn + h * HDn + 4 * v];
    }
    for (int i = tid; i < 128 * 16; i += 256) {
        int r = i >> 4, v = i & 15;
        int j = jt * 128 + r;
        float4 f = make_float4(0.f, 0.f, 0.f, 0.f);
        if (j < Jn) f = *(const float4*)&relk[j * HDn + 4 * v];
        *(float4*)&sB[r][4 * v] = f;
    }
    __syncthreads();

    float acc[4][4] = {};
    const int r0 = w * 4;
#pragma unroll
    for (int d4 = 0; d4 < 16; d4++) {
        float4 a[4], bb[4];
#pragma unroll
        for (int i = 0; i < 4; i++) a[i] = *(const float4*)&sQ[r0 + i][4 * d4];
#pragma unroll
        for (int j = 0; j < 4; j++) bb[j] = *(const float4*)&sB[lx + 32 * j][4 * d4];
#pragma unroll
        for (int i = 0; i < 4; i++)
#pragma unroll
            for (int j = 0; j < 4; j++)
                acc[i][j] += a[i].x * bb[j].x + a[i].y * bb[j].y +
                             a[i].z * bb[j].z + a[i].w * bb[j].w;
    }
#pragma unroll
    for (int i = 0; i < 4; i++) {
        int gm = mt * 32 + r0 + i;
        int bh = gm >> 10, q = gm & SMASK;
        float* dst = &g_P[((size_t)bh * Sn + q) * JPn];
#pragma unroll
        for (int j = 0; j < 4; j++) {
            int col = jt * 128 + lx + 32 * j;
            if (col < Jn) dst[col] = acc[i][j];
        }
    }
}

// ---------------------------------------------------------------------------
// Kernel 2: scores + bias gather + softmax -> g_attn
// block: (bh, 32 q-rows). Full 32x1024 score rows held in dynamic smem.
// ---------------------------------------------------------------------------
#define SM2_FLOATS (32 * Sn + 32 * 68 + 128 * 68)

__global__ void __launch_bounds__(256) k_scores(const float* __restrict__ query,
                                                const float* __restrict__ key) {
    extern __shared__ float sm[];
    float* sS = sm;                                        // 32 x 1024
    float(*sQ)[68] = (float(*)[68])(sm + 32 * Sn);         // 32 x 68
    float(*sK)[68] = (float(*)[68])(sm + 32 * Sn + 32 * 68); // 128 x 68

    const int bh = blockIdx.y, b = bh >> 4, h = bh & 15;
    const int q0 = blockIdx.x * 32;
    const int tid = threadIdx.x, w = tid >> 5, lx = tid & 31;
    const int r0 = w * 4;

    for (int i = tid; i < 32 * 16; i += 256) {
        int r = i >> 4, v = i & 15;
        *(float4*)&sQ[r][4 * v] =
            *(const float4*)&query[((size_t)b * Sn + q0 + r) * Dn + h * HDn + 4 * v];
    }

    for (int kt = 0; kt < 8; kt++) {
        const int k0 = kt * 128;
        __syncthreads();
        for (int i = tid; i < 128 * 16; i += 256) {
            int r = i >> 4, v = i & 15;
            *(float4*)&sK[r][4 * v] =
                *(const float4*)&key[((size_t)b * Sn + k0 + r) * Dn + h * HDn + 4 * v];
        }
        __syncthreads();

        float acc[4][4] = {};
#pragma unroll
        for (int d4 = 0; d4 < 16; d4++) {
            float4 a[4], bb[4];
#pragma unroll
            for (int i = 0; i < 4; i++) a[i] = *(const float4*)&sQ[r0 + i][4 * d4];
#pragma unroll
            for (int j = 0; j < 4; j++) bb[j] = *(const float4*)&sK[lx + 32 * j][4 * d4];
#pragma unroll
            for (int i = 0; i < 4; i++)
#pragma unroll
                for (int j = 0; j < 4; j++)
                    acc[i][j] += a[i].x * bb[j].x + a[i].y * bb[j].y +
                                 a[i].z * bb[j].z + a[i].w * bb[j].w;
        }
#pragma unroll
        for (int i = 0; i < 4; i++) {
            int q = q0 + r0 + i;
            const float* Prow = &g_P[((size_t)bh * Sn + q) * JPn];
#pragma unroll
            for (int j = 0; j < 4; j++) {
                int kcol = k0 + lx + 32 * j;
                int dd = (q - kcol) & SMASK;
                int idx = min(dd, 1024 - dd);
                sS[(r0 + i) * Sn + kcol] = acc[i][j] * SCALE + Prow[idx];
            }
        }
    }
    __syncthreads();

    // softmax: one warp per row (8 warps x 4 rows each), coalesced attn write
    for (int r = w; r < 32; r += 8) {
        float* rowp = sS + r * Sn;
        float m = -1e30f;
        for (int k = lx; k < Sn; k += 32) m = fmaxf(m, rowp[k]);
#pragma unroll
        for (int o = 16; o; o >>= 1) m = fmaxf(m, __shfl_xor_sync(0xffffffffu, m, o));
        float ssum = 0.f;
        for (int k = lx; k < Sn; k += 32) {
            float e = __expf(rowp[k] - m);
            rowp[k] = e;
            ssum += e;
        }
#pragma unroll
        for (int o = 16; o; o >>= 1) ssum += __shfl_xor_sync(0xffffffffu, ssum, o);
        float inv = 1.0f / ssum;
        float* op = &g_attn[((size_t)bh * Sn + q0 + r) * Sn];
        for (int k = lx; k < Sn; k += 32) op[k] = rowp[k] * inv;
    }
}

// ---------------------------------------------------------------------------
// Kernel 3: out = attn @ V   (per bh: 1024x64 = 1024x1024 @ 1024x64)
// block: 32 q-rows x 64 cols; k-tiles of 64.
// ---------------------------------------------------------------------------
__global__ void __launch_bounds__(256) k_av(const float* __restrict__ value,
                                            float* __restrict__ out) {
    __shared__ float sA[32][68];
    __shared__ float sV[64][68];
    const int bh = blockIdx.y, b = bh >> 4, h = bh & 15;
    const int q0 = blockIdx.x * 32;
    const int tid = threadIdx.x, w = tid >> 5, lx = tid & 31;
    const int r0 = w * 4;

    float acc[4][2] = {};
    for (int kt = 0; kt < 16; kt++) {
        __syncthreads();
        for (int i = tid; i < 32 * 16; i += 256) {
            int r = i >> 4, v = i & 15;
            *(float4*)&sA[r][4 * v] =
                *(const float4*)&g_attn[((size_t)bh * Sn + q0 + r) * Sn + kt * 64 + 4 * v];
        }
        for (int i = tid; i < 64 * 16; i += 256) {
            int r = i >> 4, v = i & 15;
            *(float4*)&sV[r][4 * v] =
                *(const float4*)&value[((size_t)b * Sn + kt * 64 + r) * Dn + h * HDn + 4 * v];
        }
        __syncthreads();
#pragma unroll
        for (int k4 = 0; k4 < 16; k4++) {
            float4 a[4];
#pragma unroll
            for (int i = 0; i < 4; i++) a[i] = *(const float4*)&sA[r0 + i][4 * k4];
#pragma unroll
            for (int kk = 0; kk < 4; kk++) {
                float b0 = sV[4 * k4 + kk][lx];
                float b1 = sV[4 * k4 + kk][lx + 32];
#pragma unroll
                for (int i = 0; i < 4; i++) {
                    float av = (kk == 0) ? a[i].x : (kk == 1) ? a[i].y
                             : (kk == 2) ? a[i].z : a[i].w;
                    acc[i][0] += av * b0;
                    acc[i][1] += av * b1;
                }
            }
        }
    }
#pragma unroll
    for (int i = 0; i < 4; i++) {
        float* dst = &out[((size_t)b * Sn + q0 + r0 + i) * Dn + h * HDn];
        dst[lx]      = acc[i][0];
        dst[lx + 32] = acc[i][1];
    }
}

// ---------------------------------------------------------------------------
// Kernel 4: out += Wfold @ rel_pos_v, Wfold gathered from attn on the fly.
//   Wfold[q,j] = attn[q,(q-j)&1023] + (0<j<512 ? attn[q,(q+j)&1023] : 0), j<=512
// ---------------------------------------------------------------------------
__global__ void __launch_bounds__(256) k_wrelv(const float* __restrict__ relv,
                                               float* __restrict__ out) {
    __shared__ float sA[32][68];
    __shared__ float sV[64][68];
    const int bh = blockIdx.y, b = bh >> 4, h = bh & 15;
    const int q0 = blockIdx.x * 32;
    const int tid = threadIdx.x, w = tid >> 5, lx = tid & 31;
    const int r0 = w * 4;

    float acc[4][2] = {};
    for (int jt = 0; jt < 9; jt++) {     // j tiles of 64 covering 0..575 (valid j<=512)
        __syncthreads();
        for (int i = tid; i < 32 * 64; i += 256) {
            int r = i >> 6, c = i & 63;
            int q = q0 + r;
            int j = jt * 64 + c;
            float wv = 0.f;
            if (j <= 512) {
                const float* arow = &g_attn[((size_t)bh * Sn + q) * Sn];
                wv = arow[(q - j) & SMASK];
                if (j > 0 && j < 512) wv += arow[(q + j) & SMASK];
            }
            sA[r][c] = wv;
        }
        for (int i = tid; i < 64 * 16; i += 256) {
            int r = i >> 4, v = i & 15;
            int jr = jt * 64 + r;
            float4 f = make_float4(0.f, 0.f, 0.f, 0.f);
            if (jr < Jn) f = *(const float4*)&relv[jr * HDn + 4 * v];
            *(float4*)&sV[r][4 * v] = f;
        }
        __syncthreads();
#pragma unroll
        for (int k4 = 0; k4 < 16; k4++) {
            float4 a[4];
#pragma unroll
            for (int i = 0; i < 4; i++) a[i] = *(const float4*)&sA[r0 + i][4 * k4];
#pragma unroll
            for (int kk = 0; kk < 4; kk++) {
                float b0 = sV[4 * k4 + kk][lx];
                float b1 = sV[4 * k4 + kk][lx + 32];
#pragma unroll
                for (int i = 0; i < 4; i++) {
                    float av = (kk == 0) ? a[i].x : (kk == 1) ? a[i].y
                             : (kk == 2) ? a[i].z : a[i].w;
                    acc[i][0] += av * b0;
                    acc[i][1] += av * b1;
                }
            }
        }
    }
#pragma unroll
    for (int i = 0; i < 4; i++) {
        float* dst = &out[((size_t)b * Sn + q0 + r0 + i) * Dn + h * HDn];
        dst[lx]      += acc[i][0];
        dst[lx + 32] += acc[i][1];
    }
}

// ---------------------------------------------------------------------------
// Launch: 4 sequential kernels on the capture stream.
// inputs: 0=query 1=key 2=value 3=rel_pos_k 4=rel_pos_v ; out = f32 (B,S,D)
// ---------------------------------------------------------------------------
extern "C" void kernel_launch(void* const* d_in, const int* in_sizes, int n_in,
                              void* d_out, int out_size) {
    const float* q  = (const float*)d_in[0];
    const float* k  = (const float*)d_in[1];
    const float* v  = (const float*)d_in[2];
    const float* rk = (const float*)d_in[3];
    const float* rv = (const float*)d_in[4];
    float* out = (float*)d_out;

    const size_t sm2 = (size_t)SM2_FLOATS * sizeof(float);   // ~174.6 KB
    cudaFuncSetAttribute(k_scores, cudaFuncAttributeMaxDynamicSharedMemorySize,
                         (int)sm2);

    k_relk  <<<dim3(5, 4096), 256>>>(q, rk);
    k_scores<<<dim3(32, BHn), 256, sm2>>>(q, k);
    k_av    <<<dim3(32, BHn), 256>>>(v, out);
    k_wrelv <<<dim3(32, BHn), 256>>>(rv, out);
}